// round 7
// baseline (speedup 1.0000x reference)
#include <cuda_runtime.h>
#include <cuda_bf16.h>
#include <math.h>
#include <stdint.h>

// Problem constants
#define BATCH 4
#define SLEN  2048
#define EMB   1024
#define QKVF  3072

// ---------------------------------------------------------------------------
// Device scratch (allocation-free rule: __device__ globals)
// ---------------------------------------------------------------------------
__device__ __align__(256) __nv_bfloat16 g_Xh[(size_t)BATCH*SLEN*EMB];
__device__ __align__(256) __nv_bfloat16 g_Xl[(size_t)BATCH*SLEN*EMB];
__device__ __align__(256) __nv_bfloat16 g_Wqh[(size_t)QKVF*EMB];
__device__ __align__(256) __nv_bfloat16 g_Wql[(size_t)QKVF*EMB];
__device__ __align__(256) __nv_bfloat16 g_Woh[(size_t)EMB*EMB];
__device__ __align__(256) __nv_bfloat16 g_Wol[(size_t)EMB*EMB];
__device__ __align__(256) __nv_bfloat16 g_qh[(size_t)BATCH*SLEN*EMB];
__device__ __align__(256) __nv_bfloat16 g_ql[(size_t)BATCH*SLEN*EMB];
__device__ __align__(256) __nv_bfloat16 g_kh[(size_t)BATCH*SLEN*EMB];
__device__ __align__(256) __nv_bfloat16 g_kl[(size_t)BATCH*SLEN*EMB];
__device__ __align__(256) __nv_bfloat16 g_vth[(size_t)BATCH*EMB*SLEN];  // V^T [b,e,s]
__device__ __align__(256) __nv_bfloat16 g_vtl[(size_t)BATCH*EMB*SLEN];
__device__ __align__(256) float         g_att[(size_t)BATCH*SLEN*SLEN];
__device__ __align__(256) __nv_bfloat16 g_ath[(size_t)BATCH*SLEN*SLEN];
__device__ __align__(256) __nv_bfloat16 g_atl[(size_t)BATCH*SLEN*SLEN];
__device__ __align__(256) __nv_bfloat16 g_ch[(size_t)BATCH*SLEN*EMB];
__device__ __align__(256) __nv_bfloat16 g_cl[(size_t)BATCH*SLEN*EMB];

// ---------------------------------------------------------------------------
// PTX helpers (sm_80+ only — tcgen05 rejected by compute_103 PTX target)
// ---------------------------------------------------------------------------
__device__ __forceinline__ uint32_t smem_u32(const void* p) {
    uint32_t a;
    asm("{ .reg .u64 t; cvta.to.shared.u64 t, %1; cvt.u32.u64 %0, t; }"
        : "=r"(a) : "l"(p));
    return a;
}
#define CP16(d, s)   asm volatile("cp.async.cg.shared.global [%0], [%1], 16;" :: "r"(d), "l"(s))
#define CP_COMMIT()  asm volatile("cp.async.commit_group;" ::: "memory")
#define CP_WAIT0()   asm volatile("cp.async.wait_group 0;" ::: "memory")

__device__ __forceinline__ void ldsm4(uint32_t* r, uint32_t addr) {
    asm volatile("ldmatrix.sync.aligned.m8n8.x4.shared.b16 {%0,%1,%2,%3}, [%4];"
        : "=r"(r[0]), "=r"(r[1]), "=r"(r[2]), "=r"(r[3]) : "r"(addr));
}
__device__ __forceinline__ void mma16816(float* d, const uint32_t* a, const uint32_t* b) {
    asm volatile("mma.sync.aligned.m16n8k16.row.col.f32.bf16.bf16.f32 "
        "{%0,%1,%2,%3}, {%4,%5,%6,%7}, {%8,%9}, {%0,%1,%2,%3};"
        : "+f"(d[0]), "+f"(d[1]), "+f"(d[2]), "+f"(d[3])
        : "r"(a[0]), "r"(a[1]), "r"(a[2]), "r"(a[3]), "r"(b[0]), "r"(b[1]));
}

// Tiling: CTA 128x128, BK=32, 8 warps (2x4), warp tile 64x32. 2 CTAs/SM.
#define ROWB    80                  // 32 bf16 = 64B padded to 80B
#define TILEB   (128 * ROWB)        // 10240 B per operand tile
#define STAGEB  (4 * TILEB)         // Ah, Al, Bh, Bl = 40960 B
#define GEMM_SMEM (2 * STAGEB + 128)    // 82048 B -> 2 CTAs/SM

// ---------------------------------------------------------------------------
// bf16x3 GEMM NT:  D[m,n] = alpha * sum_k A[m,k]*B[n,k]   (A,B split hi/lo)
// Software-pipelined ldmatrix: A-frags double-buffered across mt,
// B-frags double-buffered across kk.
// ---------------------------------------------------------------------------
template<int MODE>
__global__ void __launch_bounds__(256, 2)
gemm_k(const __nv_bfloat16* __restrict__ Ah, const __nv_bfloat16* __restrict__ Al,
       size_t sA, int ldA,
       const __nv_bfloat16* __restrict__ Bh, const __nv_bfloat16* __restrict__ Bl,
       size_t sB, int ldB, int K,
       float* __restrict__ outF, size_t sF, int ldF,
       __nv_bfloat16* __restrict__ oh0, __nv_bfloat16* __restrict__ ol0,
       __nv_bfloat16* __restrict__ oh1, __nv_bfloat16* __restrict__ ol1,
       __nv_bfloat16* __restrict__ oh2, __nv_bfloat16* __restrict__ ol2,
       const float* __restrict__ bias, float alpha)
{
    extern __shared__ char dsm[];
    const uint32_t sb0 = smem_u32(dsm);
    const uint32_t SB  = (sb0 + 127u) & ~127u;
    float* stg = (float*)(dsm + (SB - sb0));    // epilogue staging [128][132]

    const int tid  = threadIdx.x;
    const int wid  = tid >> 5, lane = tid & 31;
    const int wm   = wid >> 2, wn = wid & 3;    // warp grid 2x4, warp tile 64x32
    const int bx = blockIdx.x, by = blockIdx.y, z = blockIdx.z;

    const char* baseA_h = (const char*)(Ah + (size_t)z * sA + (size_t)by * 128 * ldA);
    const char* baseA_l = (const char*)(Al + (size_t)z * sA + (size_t)by * 128 * ldA);
    const char* baseB_h = (const char*)(Bh + (size_t)z * sB + (size_t)bx * 128 * ldB);
    const char* baseB_l = (const char*)(Bl + (size_t)z * sB + (size_t)bx * 128 * ldB);
    const size_t strA = (size_t)ldA * 2, strB = (size_t)ldB * 2;

    auto load_chunk = [&](int c, int s) {
        const uint32_t stb = SB + (uint32_t)s * STAGEB;
        #pragma unroll
        for (int i = 0; i < 8; i++) {
            const int id = i * 256 + tid;       // 0..2047
            const int t  = id >> 9;             // operand tile 0..3
            const int u  = id & 511;
            const int r  = u >> 2;              // row 0..127
            const int c16 = u & 3;              // 16B piece 0..3
            const char* base = (t == 0) ? baseA_h : (t == 1) ? baseA_l
                             : (t == 2) ? baseB_h : baseB_l;
            const size_t str = (t < 2) ? strA : strB;
            const char* src = base + (size_t)r * str + (size_t)c * 64 + (size_t)c16 * 16;
            const uint32_t dst = stb + (uint32_t)t * TILEB + (uint32_t)(r * ROWB + c16 * 16);
            CP16(dst, src);
        }
        CP_COMMIT();
    };

    float d[4][4][4];
    #pragma unroll
    for (int a = 0; a < 4; a++)
        #pragma unroll
        for (int b = 0; b < 4; b++)
            #pragma unroll
            for (int e = 0; e < 4; e++) d[a][b][e] = 0.0f;

    const int NC = K >> 5;
    load_chunk(0, 0);

    const uint32_t offA = (uint32_t)((wm * 64 + (lane & 7) + ((lane >> 3) & 1) * 8) * ROWB
                                     + ((lane >> 4) & 1) * 16);
    const uint32_t offB = (uint32_t)((wn * 32 + ((lane >> 4) & 1) * 8 + (lane & 7)) * ROWB
                                     + ((lane >> 3) & 1) * 16);

    // fragment double-buffers
    uint32_t ah[2][4], al[2][4], bh[2][8], bl[2][8];

    for (int c = 0; c < NC; c++) {
        CP_WAIT0();
        __syncthreads();
        const int s = c & 1;
        if (c + 1 < NC) load_chunk(c + 1, s ^ 1);

        const uint32_t stb = SB + (uint32_t)s * STAGEB;
        const uint32_t Ah_s = stb,            Al_s = stb + TILEB;
        const uint32_t Bh_s = stb + 2*TILEB,  Bl_s = stb + 3*TILEB;

        // prologue loads for this chunk: B(kk=0), A(mt=0,kk=0)
        ldsm4(&bh[0][0], Bh_s + offB);
        ldsm4(&bh[0][4], Bh_s + offB + 16 * ROWB);
        ldsm4(&bl[0][0], Bl_s + offB);
        ldsm4(&bl[0][4], Bl_s + offB + 16 * ROWB);
        ldsm4(ah[0], Ah_s + offA);
        ldsm4(al[0], Al_s + offA);

        #pragma unroll
        for (int kk = 0; kk < 2; kk++) {
            const int bb = kk & 1;
            #pragma unroll
            for (int mt = 0; mt < 4; mt++) {
                const int ab = mt & 1;
                // prefetch next fragments before consuming current
                if (mt < 3) {
                    const uint32_t o = (uint32_t)((mt + 1) * 16 * ROWB + kk * 32);
                    ldsm4(ah[ab ^ 1], Ah_s + offA + o);
                    ldsm4(al[ab ^ 1], Al_s + offA + o);
                } else if (kk == 0) {
                    ldsm4(&bh[1][0], Bh_s + offB + 32u);
                    ldsm4(&bh[1][4], Bh_s + offB + 16 * ROWB + 32u);
                    ldsm4(&bl[1][0], Bl_s + offB + 32u);
                    ldsm4(&bl[1][4], Bl_s + offB + 16 * ROWB + 32u);
                    ldsm4(ah[ab ^ 1], Ah_s + offA + 32u);
                    ldsm4(al[ab ^ 1], Al_s + offA + 32u);
                }
                #pragma unroll
                for (int nt = 0; nt < 4; nt++) {
                    mma16816(d[mt][nt], ah[ab], &bh[bb][nt * 2]);
                    mma16816(d[mt][nt], ah[ab], &bl[bb][nt * 2]);
                    mma16816(d[mt][nt], al[ab], &bh[bb][nt * 2]);
                }
            }
        }
    }
    __syncthreads();   // all warps done with smem buffers; stg reuses them

    // ---- accumulators -> smem staging (with alpha & bias) ----
    #pragma unroll
    for (int mt = 0; mt < 4; mt++) {
        #pragma unroll
        for (int nt = 0; nt < 4; nt++) {
            const int r0 = wm * 64 + mt * 16 + (lane >> 2);
            const int c0 = wn * 32 + nt * 8 + (lane & 3) * 2;
            #pragma unroll
            for (int h = 0; h < 2; h++) {
                float v0 = d[mt][nt][h * 2 + 0] * alpha;
                float v1 = d[mt][nt][h * 2 + 1] * alpha;
                if (MODE == 0 || MODE == 3) {
                    v0 += bias[bx * 128 + c0];
                    v1 += bias[bx * 128 + c0 + 1];
                }
                float2 vv = make_float2(v0, v1);
                *(float2*)&stg[(r0 + h * 8) * 132 + c0] = vv;
            }
        }
    }
    __syncthreads();

    // ---- MODE-specific writers ----
    if (MODE == 1 || MODE == 3) {
        const int row = tid >> 1, h = tid & 1;
        float* dst = outF + (size_t)z * sF + ((size_t)by * 128 + row) * ldF
                   + (size_t)bx * 128 + h * 64;
        #pragma unroll
        for (int q = 0; q < 16; q++) {
            float4 v;
            v.x = stg[row * 132 + h * 64 + q * 4 + 0];
            v.y = stg[row * 132 + h * 64 + q * 4 + 1];
            v.z = stg[row * 132 + h * 64 + q * 4 + 2];
            v.w = stg[row * 132 + h * 64 + q * 4 + 3];
            ((float4*)dst)[q] = v;
        }
    } else if (MODE == 2 || (MODE == 0 && bx < 16)) {
        __nv_bfloat16 *OH, *OL;
        if (MODE == 2)      { OH = oh0; OL = ol0; }
        else if (bx < 8)    { OH = oh0; OL = ol0; }
        else                { OH = oh1; OL = ol1; }
        #pragma unroll 1
        for (int cb = 0; cb < 4; cb++) {
            #pragma unroll 1
            for (int it = 0; it < 2; it++) {
                const int row = it * 64 + (tid >> 2);
                const int qq  = tid & 3;
                const int col = cb * 32 + qq * 8;
                const size_t rg = (size_t)z * ((size_t)gridDim.y * 128)
                                + (size_t)by * 128 + row;
                const int colE = (MODE == 2) ? (bx * 128 + col) : ((bx & 7) * 128 + col);
                union { __nv_bfloat16 b[8]; uint4 v; } Uh, Ul;
                #pragma unroll
                for (int i = 0; i < 8; i++) {
                    float v = stg[row * 132 + col + i];
                    __nv_bfloat16 hi = __float2bfloat16(v);
                    Uh.b[i] = hi;
                    Ul.b[i] = __float2bfloat16(v - __bfloat162float(hi));
                }
                const size_t off = rg * 1024 + colE;
                *(uint4*)(OH + off) = Uh.v;
                *(uint4*)(OL + off) = Ul.v;
            }
        }
    } else {  // MODE 0, V tiles (bx 16..23): transposed write to vt[b][e][s]
        const int j  = tid >> 3;       // 0..31
        const int rs = tid & 7;        // 16-row segment
        const int bidx = by >> 4;
        const int s0 = (by * 128) & 2047;
        #pragma unroll 1
        for (int cb = 0; cb < 4; cb++) {
            const int col = cb * 32 + j;
            const int colE = (bx & 7) * 128 + col;
            union { __nv_bfloat16 b[16]; uint4 v[2]; } Uh, Ul;
            #pragma unroll
            for (int i = 0; i < 16; i++) {
                float v = stg[(rs * 16 + i) * 132 + col];
                __nv_bfloat16 hi = __float2bfloat16(v);
                Uh.b[i] = hi;
                Ul.b[i] = __float2bfloat16(v - __bfloat162float(hi));
            }
            const size_t off = ((size_t)bidx * 1024 + colE) * 2048 + s0 + rs * 16;
            *(uint4*)(oh2 + off)     = Uh.v[0];
            *(uint4*)(oh2 + off + 8) = Uh.v[1];
            *(uint4*)(ol2 + off)     = Ul.v[0];
            *(uint4*)(ol2 + off + 8) = Ul.v[1];
        }
    }
}

// ---------------------------------------------------------------------------
// fp32 -> bf16 hi/lo split conversion
// ---------------------------------------------------------------------------
__global__ void conv_hl(const float4* __restrict__ x, __nv_bfloat16* __restrict__ h,
                        __nv_bfloat16* __restrict__ l, int n4)
{
    const int i = blockIdx.x * 256 + threadIdx.x;
    if (i >= n4) return;
    const float4 v = x[i];
    const float vv[4] = {v.x, v.y, v.z, v.w};
    union { __nv_bfloat16 b[4]; uint2 u; } H, L;
    #pragma unroll
    for (int k = 0; k < 4; k++) {
        __nv_bfloat16 hi = __float2bfloat16(vv[k]);
        H.b[k] = hi;
        L.b[k] = __float2bfloat16(vv[k] - __bfloat162float(hi));
    }
    *(uint2*)(h + (size_t)i * 4) = H.u;
    *(uint2*)(l + (size_t)i * 4) = L.u;
}

// ---------------------------------------------------------------------------
// Masked softmax over rows of att [8192, 2048]; emits bf16 hi/lo. Vectorized.
// ---------------------------------------------------------------------------
__global__ void __launch_bounds__(256)
softmax_k(const float* __restrict__ att, const int* __restrict__ mask,
          __nv_bfloat16* __restrict__ oh, __nv_bfloat16* __restrict__ ol)
{
    const size_t row = blockIdx.x;
    const float4* a4 = (const float4*)(att  + row * (size_t)SLEN);
    const int4*   m4 = (const int4*)  (mask + row * (size_t)SLEN);
    const int tid = threadIdx.x;

    float v[8];
    const float4 x0 = a4[tid], x1 = a4[tid + 256];
    const int4   q0 = m4[tid], q1 = m4[tid + 256];
    v[0] = q0.x ? x0.x : -INFINITY;
    v[1] = q0.y ? x0.y : -INFINITY;
    v[2] = q0.z ? x0.z : -INFINITY;
    v[3] = q0.w ? x0.w : -INFINITY;
    v[4] = q1.x ? x1.x : -INFINITY;
    v[5] = q1.y ? x1.y : -INFINITY;
    v[6] = q1.z ? x1.z : -INFINITY;
    v[7] = q1.w ? x1.w : -INFINITY;

    float lmax = v[0];
    #pragma unroll
    for (int i = 1; i < 8; i++) lmax = fmaxf(lmax, v[i]);

    __shared__ float smax[8], ssum[8];
    #pragma unroll
    for (int o = 16; o > 0; o >>= 1)
        lmax = fmaxf(lmax, __shfl_xor_sync(0xffffffffu, lmax, o));
    if ((tid & 31) == 0) smax[tid >> 5] = lmax;
    __syncthreads();
    const float gmax = fmaxf(fmaxf(fmaxf(smax[0], smax[1]), fmaxf(smax[2], smax[3])),
                             fmaxf(fmaxf(smax[4], smax[5]), fmaxf(smax[6], smax[7])));
    float lsum = 0.0f;
    #pragma unroll
    for (int i = 0; i < 8; i++) { v[i] = __expf(v[i] - gmax); lsum += v[i]; }
    #pragma unroll
    for (int o = 16; o > 0; o >>= 1)
        lsum += __shfl_xor_sync(0xffffffffu, lsum, o);
    if ((tid & 31) == 0) ssum[tid >> 5] = lsum;
    __syncthreads();
    const float gsum = (ssum[0] + ssum[1]) + (ssum[2] + ssum[3])
                     + (ssum[4] + ssum[5]) + (ssum[6] + ssum[7]);
    const float inv = 1.0f / gsum;

    union { __nv_bfloat16 b[4]; uint2 u; } H0, L0, H1, L1;
    #pragma unroll
    for (int i = 0; i < 4; i++) {
        const float p = v[i] * inv;
        const __nv_bfloat16 hi = __float2bfloat16(p);
        H0.b[i] = hi;
        L0.b[i] = __float2bfloat16(p - __bfloat162float(hi));
    }
    #pragma unroll
    for (int i = 0; i < 4; i++) {
        const float p = v[4 + i] * inv;
        const __nv_bfloat16 hi = __float2bfloat16(p);
        H1.b[i] = hi;
        L1.b[i] = __float2bfloat16(p - __bfloat162float(hi));
    }
    const size_t base = row * (size_t)SLEN;
    *(uint2*)(oh + base + tid * 4)        = H0.u;
    *(uint2*)(ol + base + tid * 4)        = L0.u;
    *(uint2*)(oh + base + 1024 + tid * 4) = H1.u;
    *(uint2*)(ol + base + 1024 + tid * 4) = L1.u;
}

// ---------------------------------------------------------------------------
extern "C" void kernel_launch(void* const* d_in, const int* in_sizes, int n_in,
                              void* d_out, int out_size)
{
    const float* X     = (const float*)d_in[0];
    const int*   mask  = (const int*)  d_in[1];
    const float* W_qkv = (const float*)d_in[2];
    const float* b_qkv = (const float*)d_in[3];
    const float* W_out = (const float*)d_in[4];
    const float* b_out = (const float*)d_in[5];
    float*       out   = (float*)d_out;

    __nv_bfloat16 *Xh, *Xl, *Wqh, *Wql, *Woh, *Wol;
    __nv_bfloat16 *qh, *ql, *kh, *kl, *vth, *vtl, *ath, *atl, *ch, *cl;
    float* att;
    cudaGetSymbolAddress((void**)&Xh,  g_Xh);  cudaGetSymbolAddress((void**)&Xl,  g_Xl);
    cudaGetSymbolAddress((void**)&Wqh, g_Wqh); cudaGetSymbolAddress((void**)&Wql, g_Wql);
    cudaGetSymbolAddress((void**)&Woh, g_Woh); cudaGetSymbolAddress((void**)&Wol, g_Wol);
    cudaGetSymbolAddress((void**)&qh,  g_qh);  cudaGetSymbolAddress((void**)&ql,  g_ql);
    cudaGetSymbolAddress((void**)&kh,  g_kh);  cudaGetSymbolAddress((void**)&kl,  g_kl);
    cudaGetSymbolAddress((void**)&vth, g_vth); cudaGetSymbolAddress((void**)&vtl, g_vtl);
    cudaGetSymbolAddress((void**)&att, g_att);
    cudaGetSymbolAddress((void**)&ath, g_ath); cudaGetSymbolAddress((void**)&atl, g_atl);
    cudaGetSymbolAddress((void**)&ch,  g_ch);  cudaGetSymbolAddress((void**)&cl,  g_cl);

    cudaFuncSetAttribute(gemm_k<0>, cudaFuncAttributeMaxDynamicSharedMemorySize, GEMM_SMEM);
    cudaFuncSetAttribute(gemm_k<1>, cudaFuncAttributeMaxDynamicSharedMemorySize, GEMM_SMEM);
    cudaFuncSetAttribute(gemm_k<2>, cudaFuncAttributeMaxDynamicSharedMemorySize, GEMM_SMEM);
    cudaFuncSetAttribute(gemm_k<3>, cudaFuncAttributeMaxDynamicSharedMemorySize, GEMM_SMEM);

    // Convert inputs to bf16 hi/lo
    conv_hl<<<(BATCH*SLEN*EMB/4 + 255)/256, 256>>>((const float4*)X, Xh, Xl, BATCH*SLEN*EMB/4);
    conv_hl<<<(QKVF*EMB/4 + 255)/256, 256>>>((const float4*)W_qkv, Wqh, Wql, QKVF*EMB/4);
    conv_hl<<<(EMB*EMB/4 + 255)/256, 256>>>((const float4*)W_out, Woh, Wol, EMB*EMB/4);

    // 1) qkv = X @ W_qkv^T + b  -> q/k hi-lo (row-major), V transposed hi-lo
    gemm_k<0><<<dim3(QKVF/128, (BATCH*SLEN)/128, 1), 256, GEMM_SMEM>>>(
        Xh, Xl, 0, EMB, Wqh, Wql, 0, EMB, EMB,
        nullptr, 0, 0, qh, ql, kh, kl, vth, vtl, b_qkv, 1.0f);

    // 2) att = (Q @ K^T) / 32   (fp32 out, per batch)
    gemm_k<1><<<dim3(SLEN/128, SLEN/128, BATCH), 256, GEMM_SMEM>>>(
        qh, ql, (size_t)SLEN*EMB, EMB, kh, kl, (size_t)SLEN*EMB, EMB, EMB,
        att, (size_t)SLEN*SLEN, SLEN,
        nullptr, nullptr, nullptr, nullptr, nullptr, nullptr, nullptr, 0.03125f);

    // 3) masked softmax -> att hi/lo
    softmax_k<<<BATCH*SLEN, 256>>>(att, mask, ath, atl);

    // 4) ctx = att @ V  (B = V^T, NT)  -> ctx hi/lo
    gemm_k<2><<<dim3(EMB/128, SLEN/128, BATCH), 256, GEMM_SMEM>>>(
        ath, atl, (size_t)SLEN*SLEN, SLEN, vth, vtl, (size_t)EMB*SLEN, SLEN, SLEN,
        nullptr, 0, 0, ch, cl, nullptr, nullptr, nullptr, nullptr, nullptr, 1.0f);

    // 5) out = ctx @ W_out^T + b
    gemm_k<3><<<dim3(EMB/128, (BATCH*SLEN)/128, 1), 256, GEMM_SMEM>>>(
        ch, cl, 0, EMB, Woh, Wol, 0, EMB, EMB,
        out, 0, EMB,
        nullptr, nullptr, nullptr, nullptr, nullptr, nullptr, b_out, 1.0f);
}

// round 8
// speedup vs baseline: 1.0061x; 1.0061x over previous
#include <cuda_runtime.h>
#include <cuda_bf16.h>
#include <math.h>
#include <stdint.h>

// Problem constants
#define BATCH 4
#define SLEN  2048
#define EMB   1024
#define QKVF  3072

// ---------------------------------------------------------------------------
// Device scratch (allocation-free rule: __device__ globals)
// ---------------------------------------------------------------------------
__device__ __align__(256) __nv_bfloat16 g_Xh[(size_t)BATCH*SLEN*EMB];
__device__ __align__(256) __nv_bfloat16 g_Xl[(size_t)BATCH*SLEN*EMB];
__device__ __align__(256) __nv_bfloat16 g_Wqh[(size_t)QKVF*EMB];
__device__ __align__(256) __nv_bfloat16 g_Wql[(size_t)QKVF*EMB];
__device__ __align__(256) __nv_bfloat16 g_Woh[(size_t)EMB*EMB];
__device__ __align__(256) __nv_bfloat16 g_Wol[(size_t)EMB*EMB];
__device__ __align__(256) __nv_bfloat16 g_qh[(size_t)BATCH*SLEN*EMB];
__device__ __align__(256) __nv_bfloat16 g_ql[(size_t)BATCH*SLEN*EMB];
__device__ __align__(256) __nv_bfloat16 g_kh[(size_t)BATCH*SLEN*EMB];
__device__ __align__(256) __nv_bfloat16 g_kl[(size_t)BATCH*SLEN*EMB];
__device__ __align__(256) __nv_bfloat16 g_vth[(size_t)BATCH*EMB*SLEN];  // V^T [b,e,s]
__device__ __align__(256) __nv_bfloat16 g_vtl[(size_t)BATCH*EMB*SLEN];
__device__ __align__(256) float         g_att[(size_t)BATCH*SLEN*SLEN];
__device__ __align__(256) __nv_bfloat16 g_ath[(size_t)BATCH*SLEN*SLEN];
__device__ __align__(256) __nv_bfloat16 g_atl[(size_t)BATCH*SLEN*SLEN];
__device__ __align__(256) __nv_bfloat16 g_ch[(size_t)BATCH*SLEN*EMB];
__device__ __align__(256) __nv_bfloat16 g_cl[(size_t)BATCH*SLEN*EMB];

// ---------------------------------------------------------------------------
// PTX helpers (sm_80+ only — tcgen05 rejected by compute_103 PTX target)
// ---------------------------------------------------------------------------
__device__ __forceinline__ uint32_t smem_u32(const void* p) {
    uint32_t a;
    asm("{ .reg .u64 t; cvta.to.shared.u64 t, %1; cvt.u32.u64 %0, t; }"
        : "=r"(a) : "l"(p));
    return a;
}
#define CP16(d, s)   asm volatile("cp.async.cg.shared.global [%0], [%1], 16;" :: "r"(d), "l"(s))
#define CP_COMMIT()  asm volatile("cp.async.commit_group;" ::: "memory")
#define CP_WAIT0()   asm volatile("cp.async.wait_group 0;" ::: "memory")

__device__ __forceinline__ void ldsm4(uint32_t* r, uint32_t addr) {
    asm volatile("ldmatrix.sync.aligned.m8n8.x4.shared.b16 {%0,%1,%2,%3}, [%4];"
        : "=r"(r[0]), "=r"(r[1]), "=r"(r[2]), "=r"(r[3]) : "r"(addr));
}
__device__ __forceinline__ void mma16816(float* d, const uint32_t* a, const uint32_t* b) {
    asm volatile("mma.sync.aligned.m16n8k16.row.col.f32.bf16.bf16.f32 "
        "{%0,%1,%2,%3}, {%4,%5,%6,%7}, {%8,%9}, {%0,%1,%2,%3};"
        : "+f"(d[0]), "+f"(d[1]), "+f"(d[2]), "+f"(d[3])
        : "r"(a[0]), "r"(a[1]), "r"(a[2]), "r"(a[3]), "r"(b[0]), "r"(b[1]));
}

// Tiling: CTA 128x128, BK=32, 8 warps (2x4), warp tile 64x32. 2 CTAs/SM.
#define ROWB    80                  // 32 bf16 = 64B padded to 80B
#define TILEB   (128 * ROWB)        // 10240 B per operand tile
#define STAGEB  (4 * TILEB)         // Ah, Al, Bh, Bl = 40960 B
#define GEMM_SMEM (2 * STAGEB + 128)    // 82048 B -> 2 CTAs/SM
#define PGRID   296                 // persistent grid: 2 CTAs x 148 SMs

// ---------------------------------------------------------------------------
// bf16x3 GEMM NT, persistent CTAs:  D[m,n] = alpha * sum_k A[m,k]*B[n,k]
// MODE 0: qkv epilogue (bias; q/k hi-lo row-major; V transposed hi-lo)
// MODE 1: scores       (fp32 out, batched, alpha=1/32)
// MODE 2: ctx          (hi/lo row-major out)
// MODE 3: out proj     (bias; fp32 out)
// ---------------------------------------------------------------------------
template<int MODE>
__global__ void __launch_bounds__(256, 2)
gemm_k(const __nv_bfloat16* __restrict__ Ah, const __nv_bfloat16* __restrict__ Al,
       size_t sA, int ldA,
       const __nv_bfloat16* __restrict__ Bh, const __nv_bfloat16* __restrict__ Bl,
       size_t sB, int ldB, int K,
       float* __restrict__ outF, size_t sF, int ldF,
       __nv_bfloat16* __restrict__ oh0, __nv_bfloat16* __restrict__ ol0,
       __nv_bfloat16* __restrict__ oh1, __nv_bfloat16* __restrict__ ol1,
       __nv_bfloat16* __restrict__ oh2, __nv_bfloat16* __restrict__ ol2,
       const float* __restrict__ bias, float alpha,
       int gx, int gy, int ntiles)
{
    extern __shared__ char dsm[];
    const uint32_t sb0 = smem_u32(dsm);
    const uint32_t SB  = (sb0 + 127u) & ~127u;
    float* stg = (float*)(dsm + (SB - sb0));    // epilogue staging [128][132]

    const int tid  = threadIdx.x;
    const int wid  = tid >> 5, lane = tid & 31;
    const int wm   = wid >> 2, wn = wid & 3;    // warp grid 2x4, warp tile 64x32
    const size_t strA = (size_t)ldA * 2, strB = (size_t)ldB * 2;

    const uint32_t offA = (uint32_t)((wm * 64 + (lane & 7) + ((lane >> 3) & 1) * 8) * ROWB
                                     + ((lane >> 4) & 1) * 16);
    const uint32_t offB = (uint32_t)((wn * 32 + ((lane >> 4) & 1) * 8 + (lane & 7)) * ROWB
                                     + ((lane >> 3) & 1) * 16);
    const int NC = K >> 5;

    for (int t = blockIdx.x; t < ntiles; t += gridDim.x) {
        const int bx  = t % gx;
        const int tyz = t / gx;
        const int by  = tyz % gy;
        const int z   = tyz / gy;

        const char* baseA_h = (const char*)(Ah + (size_t)z * sA + (size_t)by * 128 * ldA);
        const char* baseA_l = (const char*)(Al + (size_t)z * sA + (size_t)by * 128 * ldA);
        const char* baseB_h = (const char*)(Bh + (size_t)z * sB + (size_t)bx * 128 * ldB);
        const char* baseB_l = (const char*)(Bl + (size_t)z * sB + (size_t)bx * 128 * ldB);

        auto load_chunk = [&](int c, int s) {
            const uint32_t stb = SB + (uint32_t)s * STAGEB;
            #pragma unroll
            for (int i = 0; i < 8; i++) {
                const int id = i * 256 + tid;       // 0..2047
                const int tt = id >> 9;             // operand tile 0..3
                const int u  = id & 511;
                const int r  = u >> 2;              // row 0..127
                const int c16 = u & 3;              // 16B piece 0..3
                const char* base = (tt == 0) ? baseA_h : (tt == 1) ? baseA_l
                                 : (tt == 2) ? baseB_h : baseB_l;
                const size_t str = (tt < 2) ? strA : strB;
                const char* src = base + (size_t)r * str + (size_t)c * 64 + (size_t)c16 * 16;
                const uint32_t dst = stb + (uint32_t)tt * TILEB + (uint32_t)(r * ROWB + c16 * 16);
                CP16(dst, src);
            }
            CP_COMMIT();
        };

        float d[4][4][4];
        #pragma unroll
        for (int a = 0; a < 4; a++)
            #pragma unroll
            for (int b = 0; b < 4; b++)
                #pragma unroll
                for (int e = 0; e < 4; e++) d[a][b][e] = 0.0f;

        load_chunk(0, 0);

        for (int c = 0; c < NC; c++) {
            CP_WAIT0();
            __syncthreads();
            const int s = c & 1;
            if (c + 1 < NC) load_chunk(c + 1, s ^ 1);

            const uint32_t stb = SB + (uint32_t)s * STAGEB;
            const uint32_t Ah_s = stb,            Al_s = stb + TILEB;
            const uint32_t Bh_s = stb + 2*TILEB,  Bl_s = stb + 3*TILEB;

            #pragma unroll
            for (int kk = 0; kk < 2; kk++) {
                uint32_t bh[8], bl[8];
                ldsm4(&bh[0], Bh_s + offB + (uint32_t)(kk * 32));
                ldsm4(&bh[4], Bh_s + offB + (uint32_t)(16 * ROWB + kk * 32));
                ldsm4(&bl[0], Bl_s + offB + (uint32_t)(kk * 32));
                ldsm4(&bl[4], Bl_s + offB + (uint32_t)(16 * ROWB + kk * 32));
                #pragma unroll
                for (int mt = 0; mt < 4; mt++) {
                    uint32_t ah[4], al[4];
                    const uint32_t o = (uint32_t)(mt * 16 * ROWB) + (uint32_t)(kk * 32);
                    ldsm4(ah, Ah_s + offA + o);
                    ldsm4(al, Al_s + offA + o);
                    #pragma unroll
                    for (int nt = 0; nt < 4; nt++) {
                        mma16816(d[mt][nt], ah, &bh[nt * 2]);
                        mma16816(d[mt][nt], ah, &bl[nt * 2]);
                        mma16816(d[mt][nt], al, &bh[nt * 2]);
                    }
                }
            }
        }
        __syncthreads();   // all warps done with smem buffers; stg reuses them

        // ---- accumulators -> smem staging (with alpha & bias) ----
        #pragma unroll
        for (int mt = 0; mt < 4; mt++) {
            #pragma unroll
            for (int nt = 0; nt < 4; nt++) {
                const int r0 = wm * 64 + mt * 16 + (lane >> 2);
                const int c0 = wn * 32 + nt * 8 + (lane & 3) * 2;
                #pragma unroll
                for (int h = 0; h < 2; h++) {
                    float v0 = d[mt][nt][h * 2 + 0] * alpha;
                    float v1 = d[mt][nt][h * 2 + 1] * alpha;
                    if (MODE == 0 || MODE == 3) {
                        v0 += bias[bx * 128 + c0];
                        v1 += bias[bx * 128 + c0 + 1];
                    }
                    float2 vv = make_float2(v0, v1);
                    *(float2*)&stg[(r0 + h * 8) * 132 + c0] = vv;
                }
            }
        }
        __syncthreads();

        // ---- MODE-specific writers ----
        if (MODE == 1 || MODE == 3) {
            const int row = tid >> 1, h = tid & 1;
            float* dst = outF + (size_t)z * sF + ((size_t)by * 128 + row) * ldF
                       + (size_t)bx * 128 + h * 64;
            #pragma unroll
            for (int q = 0; q < 16; q++) {
                float4 v;
                v.x = stg[row * 132 + h * 64 + q * 4 + 0];
                v.y = stg[row * 132 + h * 64 + q * 4 + 1];
                v.z = stg[row * 132 + h * 64 + q * 4 + 2];
                v.w = stg[row * 132 + h * 64 + q * 4 + 3];
                ((float4*)dst)[q] = v;
            }
        } else if (MODE == 2 || (MODE == 0 && bx < 16)) {
            __nv_bfloat16 *OH, *OL;
            if (MODE == 2)      { OH = oh0; OL = ol0; }
            else if (bx < 8)    { OH = oh0; OL = ol0; }
            else                { OH = oh1; OL = ol1; }
            #pragma unroll 1
            for (int cb = 0; cb < 4; cb++) {
                #pragma unroll 1
                for (int it = 0; it < 2; it++) {
                    const int row = it * 64 + (tid >> 2);
                    const int qq  = tid & 3;
                    const int col = cb * 32 + qq * 8;
                    const size_t rg = (size_t)z * ((size_t)gy * 128)
                                    + (size_t)by * 128 + row;
                    const int colE = (MODE == 2) ? (bx * 128 + col) : ((bx & 7) * 128 + col);
                    union { __nv_bfloat16 b[8]; uint4 v; } Uh, Ul;
                    #pragma unroll
                    for (int i = 0; i < 8; i++) {
                        float v = stg[row * 132 + col + i];
                        __nv_bfloat16 hi = __float2bfloat16(v);
                        Uh.b[i] = hi;
                        Ul.b[i] = __float2bfloat16(v - __bfloat162float(hi));
                    }
                    const size_t off = rg * 1024 + colE;
                    *(uint4*)(OH + off) = Uh.v;
                    *(uint4*)(OL + off) = Ul.v;
                }
            }
        } else {  // MODE 0, V tiles (bx 16..23): transposed write to vt[b][e][s]
            const int j  = tid >> 3;       // 0..31
            const int rs = tid & 7;        // 16-row segment
            const int bidx = by >> 4;
            const int s0 = (by * 128) & 2047;
            #pragma unroll 1
            for (int cb = 0; cb < 4; cb++) {
                const int col = cb * 32 + j;
                const int colE = (bx & 7) * 128 + col;
                union { __nv_bfloat16 b[16]; uint4 v[2]; } Uh, Ul;
                #pragma unroll
                for (int i = 0; i < 16; i++) {
                    float v = stg[(rs * 16 + i) * 132 + col];
                    __nv_bfloat16 hi = __float2bfloat16(v);
                    Uh.b[i] = hi;
                    Ul.b[i] = __float2bfloat16(v - __bfloat162float(hi));
                }
                const size_t off = ((size_t)bidx * 1024 + colE) * 2048 + s0 + rs * 16;
                *(uint4*)(oh2 + off)     = Uh.v[0];
                *(uint4*)(oh2 + off + 8) = Uh.v[1];
                *(uint4*)(ol2 + off)     = Ul.v[0];
                *(uint4*)(ol2 + off + 8) = Ul.v[1];
            }
        }
        __syncthreads();   // stg free before next tile's loads overwrite it
    }
}

// ---------------------------------------------------------------------------
// fp32 -> bf16 hi/lo split conversion: X, W_qkv, W_out in ONE launch
// ---------------------------------------------------------------------------
__global__ void conv_all(const float4* __restrict__ X,  __nv_bfloat16* __restrict__ Xh,  __nv_bfloat16* __restrict__ Xl,  int n1,
                         const float4* __restrict__ Wq, __nv_bfloat16* __restrict__ Wqh, __nv_bfloat16* __restrict__ Wql, int n2,
                         const float4* __restrict__ Wo, __nv_bfloat16* __restrict__ Woh, __nv_bfloat16* __restrict__ Wol, int n3)
{
    int i = blockIdx.x * 256 + threadIdx.x;
    const float4* src; __nv_bfloat16 *h, *l;
    if (i < n1)            { src = X;  h = Xh;  l = Xl;  }
    else if (i < n1 + n2)  { src = Wq; h = Wqh; l = Wql; i -= n1; }
    else if (i < n1+n2+n3) { src = Wo; h = Woh; l = Wol; i -= n1 + n2; }
    else return;
    const float4 v = src[i];
    const float vv[4] = {v.x, v.y, v.z, v.w};
    union { __nv_bfloat16 b[4]; uint2 u; } H, L;
    #pragma unroll
    for (int k = 0; k < 4; k++) {
        __nv_bfloat16 hi = __float2bfloat16(vv[k]);
        H.b[k] = hi;
        L.b[k] = __float2bfloat16(vv[k] - __bfloat162float(hi));
    }
    *(uint2*)(h + (size_t)i * 4) = H.u;
    *(uint2*)(l + (size_t)i * 4) = L.u;
}

// ---------------------------------------------------------------------------
// Masked softmax over rows of att [8192, 2048]; emits bf16 hi/lo. Vectorized.
// ---------------------------------------------------------------------------
__global__ void __launch_bounds__(256)
softmax_k(const float* __restrict__ att, const int* __restrict__ mask,
          __nv_bfloat16* __restrict__ oh, __nv_bfloat16* __restrict__ ol)
{
    const size_t row = blockIdx.x;
    const float4* a4 = (const float4*)(att  + row * (size_t)SLEN);
    const int4*   m4 = (const int4*)  (mask + row * (size_t)SLEN);
    const int tid = threadIdx.x;

    float v[8];
    const float4 x0 = a4[tid], x1 = a4[tid + 256];
    const int4   q0 = m4[tid], q1 = m4[tid + 256];
    v[0] = q0.x ? x0.x : -INFINITY;
    v[1] = q0.y ? x0.y : -INFINITY;
    v[2] = q0.z ? x0.z : -INFINITY;
    v[3] = q0.w ? x0.w : -INFINITY;
    v[4] = q1.x ? x1.x : -INFINITY;
    v[5] = q1.y ? x1.y : -INFINITY;
    v[6] = q1.z ? x1.z : -INFINITY;
    v[7] = q1.w ? x1.w : -INFINITY;

    float lmax = v[0];
    #pragma unroll
    for (int i = 1; i < 8; i++) lmax = fmaxf(lmax, v[i]);

    __shared__ float smax[8], ssum[8];
    #pragma unroll
    for (int o = 16; o > 0; o >>= 1)
        lmax = fmaxf(lmax, __shfl_xor_sync(0xffffffffu, lmax, o));
    if ((tid & 31) == 0) smax[tid >> 5] = lmax;
    __syncthreads();
    const float gmax = fmaxf(fmaxf(fmaxf(smax[0], smax[1]), fmaxf(smax[2], smax[3])),
                             fmaxf(fmaxf(smax[4], smax[5]), fmaxf(smax[6], smax[7])));
    float lsum = 0.0f;
    #pragma unroll
    for (int i = 0; i < 8; i++) { v[i] = __expf(v[i] - gmax); lsum += v[i]; }
    #pragma unroll
    for (int o = 16; o > 0; o >>= 1)
        lsum += __shfl_xor_sync(0xffffffffu, lsum, o);
    if ((tid & 31) == 0) ssum[tid >> 5] = lsum;
    __syncthreads();
    const float gsum = (ssum[0] + ssum[1]) + (ssum[2] + ssum[3])
                     + (ssum[4] + ssum[5]) + (ssum[6] + ssum[7]);
    const float inv = 1.0f / gsum;

    union { __nv_bfloat16 b[4]; uint2 u; } H0, L0, H1, L1;
    #pragma unroll
    for (int i = 0; i < 4; i++) {
        const float p = v[i] * inv;
        const __nv_bfloat16 hi = __float2bfloat16(p);
        H0.b[i] = hi;
        L0.b[i] = __float2bfloat16(p - __bfloat162float(hi));
    }
    #pragma unroll
    for (int i = 0; i < 4; i++) {
        const float p = v[4 + i] * inv;
        const __nv_bfloat16 hi = __float2bfloat16(p);
        H1.b[i] = hi;
        L1.b[i] = __float2bfloat16(p - __bfloat162float(hi));
    }
    const size_t base = row * (size_t)SLEN;
    *(uint2*)(oh + base + tid * 4)        = H0.u;
    *(uint2*)(ol + base + tid * 4)        = L0.u;
    *(uint2*)(oh + base + 1024 + tid * 4) = H1.u;
    *(uint2*)(ol + base + 1024 + tid * 4) = L1.u;
}

// ---------------------------------------------------------------------------
extern "C" void kernel_launch(void* const* d_in, const int* in_sizes, int n_in,
                              void* d_out, int out_size)
{
    const float* X     = (const float*)d_in[0];
    const int*   mask  = (const int*)  d_in[1];
    const float* W_qkv = (const float*)d_in[2];
    const float* b_qkv = (const float*)d_in[3];
    const float* W_out = (const float*)d_in[4];
    const float* b_out = (const float*)d_in[5];
    float*       out   = (float*)d_out;

    __nv_bfloat16 *Xh, *Xl, *Wqh, *Wql, *Woh, *Wol;
    __nv_bfloat16 *qh, *ql, *kh, *kl, *vth, *vtl, *ath, *atl, *ch, *cl;
    float* att;
    cudaGetSymbolAddress((void**)&Xh,  g_Xh);  cudaGetSymbolAddress((void**)&Xl,  g_Xl);
    cudaGetSymbolAddress((void**)&Wqh, g_Wqh); cudaGetSymbolAddress((void**)&Wql, g_Wql);
    cudaGetSymbolAddress((void**)&Woh, g_Woh); cudaGetSymbolAddress((void**)&Wol, g_Wol);
    cudaGetSymbolAddress((void**)&qh,  g_qh);  cudaGetSymbolAddress((void**)&ql,  g_ql);
    cudaGetSymbolAddress((void**)&kh,  g_kh);  cudaGetSymbolAddress((void**)&kl,  g_kl);
    cudaGetSymbolAddress((void**)&vth, g_vth); cudaGetSymbolAddress((void**)&vtl, g_vtl);
    cudaGetSymbolAddress((void**)&att, g_att);
    cudaGetSymbolAddress((void**)&ath, g_ath); cudaGetSymbolAddress((void**)&atl, g_atl);
    cudaGetSymbolAddress((void**)&ch,  g_ch);  cudaGetSymbolAddress((void**)&cl,  g_cl);

    cudaFuncSetAttribute(gemm_k<0>, cudaFuncAttributeMaxDynamicSharedMemorySize, GEMM_SMEM);
    cudaFuncSetAttribute(gemm_k<1>, cudaFuncAttributeMaxDynamicSharedMemorySize, GEMM_SMEM);
    cudaFuncSetAttribute(gemm_k<2>, cudaFuncAttributeMaxDynamicSharedMemorySize, GEMM_SMEM);
    cudaFuncSetAttribute(gemm_k<3>, cudaFuncAttributeMaxDynamicSharedMemorySize, GEMM_SMEM);

    // Convert inputs to bf16 hi/lo (single launch)
    {
        const int n1 = BATCH*SLEN*EMB/4, n2 = QKVF*EMB/4, n3 = EMB*EMB/4;
        conv_all<<<(n1 + n2 + n3 + 255)/256, 256>>>(
            (const float4*)X, Xh, Xl, n1,
            (const float4*)W_qkv, Wqh, Wql, n2,
            (const float4*)W_out, Woh, Wol, n3);
    }

    // 1) qkv = X @ W_qkv^T + b  -> q/k hi-lo (row-major), V transposed hi-lo
    gemm_k<0><<<PGRID, 256, GEMM_SMEM>>>(
        Xh, Xl, 0, EMB, Wqh, Wql, 0, EMB, EMB,
        nullptr, 0, 0, qh, ql, kh, kl, vth, vtl, b_qkv, 1.0f,
        QKVF/128, (BATCH*SLEN)/128, (QKVF/128) * ((BATCH*SLEN)/128));

    // 2) att = (Q @ K^T) / 32   (fp32 out, per batch)
    gemm_k<1><<<PGRID, 256, GEMM_SMEM>>>(
        qh, ql, (size_t)SLEN*EMB, EMB, kh, kl, (size_t)SLEN*EMB, EMB, EMB,
        att, (size_t)SLEN*SLEN, SLEN,
        nullptr, nullptr, nullptr, nullptr, nullptr, nullptr, nullptr, 0.03125f,
        SLEN/128, SLEN/128, (SLEN/128) * (SLEN/128) * BATCH);

    // 3) masked softmax -> att hi/lo
    softmax_k<<<BATCH*SLEN, 256>>>(att, mask, ath, atl);

    // 4) ctx = att @ V  (B = V^T, NT)  -> ctx hi/lo
    gemm_k<2><<<PGRID, 256, GEMM_SMEM>>>(
        ath, atl, (size_t)SLEN*SLEN, SLEN, vth, vtl, (size_t)EMB*SLEN, SLEN, SLEN,
        nullptr, 0, 0, ch, cl, nullptr, nullptr, nullptr, nullptr, nullptr, 1.0f,
        EMB/128, SLEN/128, (EMB/128) * (SLEN/128) * BATCH);

    // 5) out = ctx @ W_out^T + b
    gemm_k<3><<<PGRID, 256, GEMM_SMEM>>>(
        ch, cl, 0, EMB, Woh, Wol, 0, EMB, EMB,
        out, 0, EMB,
        nullptr, nullptr, nullptr, nullptr, nullptr, nullptr, b_out, 1.0f,
        EMB/128, (BATCH*SLEN)/128, (EMB/128) * ((BATCH*SLEN)/128));
}